// round 7
// baseline (speedup 1.0000x reference)
#include <cuda_runtime.h>
#include <math.h>

#define H_   2048
#define HQ_  16
#define HKV_ 8
#define DH_  128
#define CHUNK_ 512
#define MAXCH_ 128
#define SCALE_ 0.08838834764831845f   // 1/sqrt(128)
#define EPS_ 1e-6f

// ------------------------- scratch (device globals, no allocs) --------------
__device__ float g_proj[4096];                 // raw q(2048) | k(1024) | v(1024)
__device__ float g_q[HQ_*DH_];                 // normed+roped q
__device__ float g_k[HKV_*DH_];                // normed+roped k_new
__device__ float g_v[HKV_*DH_];                // v_new
__device__ float g_m[HQ_*MAXCH_];
__device__ float g_l[HQ_*MAXCH_];
__device__ float g_acc[HQ_*MAXCH_*DH_];
__device__ float g_attn[HQ_*DH_];              // attention out, head-major

__device__ __forceinline__ float warpSum(float v) {
    #pragma unroll
    for (int o = 16; o; o >>= 1) v += __shfl_xor_sync(0xffffffffu, v, o);
    return v;
}
__device__ __forceinline__ float warpMax(float v) {
    #pragma unroll
    for (int o = 16; o; o >>= 1) v = fmaxf(v, __shfl_xor_sync(0xffffffffu, v, o));
    return v;
}

// 128-thread block reductions (4 warps)
__device__ __forceinline__ float blockSum128(float v, float* red, int t) {
    float ws = warpSum(v);
    if ((t & 31) == 0) red[t >> 5] = ws;
    __syncthreads();
    float out = red[0] + red[1] + red[2] + red[3];
    __syncthreads();
    return out;
}
__device__ __forceinline__ float blockMax128(float v, float* red, int t) {
    float ws = warpMax(v);
    if ((t & 31) == 0) red[t >> 5] = ws;
    __syncthreads();
    float out = fmaxf(fmaxf(red[0], red[1]), fmaxf(red[2], red[3]));
    __syncthreads();
    return out;
}

// ------------------------- 1: QKV projection (R2 shape) ----------------------
__global__ void k_proj(const float* __restrict__ x,
                       const float* __restrict__ Wq,
                       const float* __restrict__ Wk,
                       const float* __restrict__ Wv) {
    int e = blockIdx.x;
    const float* W = (e < 2048) ? (Wq + (size_t)e * H_)
                   : (e < 3072) ? (Wk + (size_t)(e - 2048) * H_)
                                : (Wv + (size_t)(e - 3072) * H_);
    int t = threadIdx.x;
    const float4* W4 = (const float4*)W;
    const float4* x4 = (const float4*)x;
    float acc = 0.f;
    #pragma unroll
    for (int k = 0; k < 4; k++) {
        float4 w  = W4[t + k * 128];
        float4 xv = x4[t + k * 128];
        acc += w.x * xv.x + w.y * xv.y + w.z * xv.z + w.w * xv.w;
    }
    __shared__ float s[4];
    float ws = warpSum(acc);
    if ((t & 31) == 0) s[t >> 5] = ws;
    __syncthreads();
    if (t == 0) g_proj[e] = s[0] + s[1] + s[2] + s[3];
}

// ------------------------- 2: RMSNorm + RoPE + copies (R2) -------------------
__global__ void k_norm_rope(const float* __restrict__ cosv,
                            const float* __restrict__ sinv,
                            const float* __restrict__ qw,
                            const float* __restrict__ kw,
                            float* __restrict__ out) {
    int b = blockIdx.x, t = threadIdx.x;
    const float* row = g_proj + b * DH_;
    if (b < 24) {
        bool isq = (b < 16);
        __shared__ float sx[DH_];
        __shared__ float red[8];
        float x = row[t];
        float ws = warpSum(x * x);
        if ((t & 31) == 0) red[t >> 5] = ws;
        __syncthreads();
        float ssum = red[0] + red[1] + red[2] + red[3];
        float rms = sqrtf(ssum * (1.0f / DH_) + EPS_);
        float xn = x / rms * (isq ? qw[t] : kw[t]);
        sx[t] = xn;
        __syncthreads();
        float rot = (t < 64) ? -sx[t + 64] : sx[t - 64];
        float o = xn * cosv[t] + rot * sinv[t];
        if (isq) {
            g_q[b * DH_ + t] = o;
        } else {
            int kv = b - 16;
            g_k[kv * DH_ + t] = o;
            out[2048 + kv * DH_ + t] = o;   // k_new output
        }
    } else {
        int kv = b - 24;
        float v = row[t];
        g_v[kv * DH_ + t] = v;
        out[3072 + kv * DH_ + t] = v;       // v output
    }
}

// ------------------------- 3: attention partials (float4 vectorized) ---------
// grid (nchunks=C/512, HKV) x 128 threads. Each block: 512 positions, 2 heads.
// Score phase: thread owns 4 consecutive c (float4 K loads, 512B/warp/iter).
// V phase: thread owns 4 dims (float4) x 4 row-streams.
__global__ void __launch_bounds__(128) k_attn_partial(
                               const float* __restrict__ kc,
                               const float* __restrict__ vc,
                               const float* __restrict__ mask,
                               int C) {
    int chunk = blockIdx.x;
    int kv = blockIdx.y;
    int t = threadIdx.x;

    __shared__ float q0s[DH_], q1s[DH_];
    __shared__ float p0s[CHUNK_], p1s[CHUNK_];
    __shared__ float red[4];
    __shared__ float4 vred[128];

    q0s[t] = g_q[(kv * 2) * DH_ + t];
    q1s[t] = g_q[(kv * 2 + 1) * DH_ + t];
    __syncthreads();

    int c0 = chunk * CHUNK_ + t * 4;               // 4 consecutive positions
    bool full = (c0 + 3 < C);

    float4 a0 = {0.f,0.f,0.f,0.f}, a1 = {0.f,0.f,0.f,0.f};
    if (full) {
        const float* kbase = kc + (size_t)kv * DH_ * C + c0;
        #pragma unroll 16
        for (int d = 0; d < DH_; d++) {
            float4 kval = *(const float4*)(kbase + (size_t)d * C);
            float q0 = q0s[d], q1 = q1s[d];
            a0.x += q0 * kval.x; a0.y += q0 * kval.y;
            a0.z += q0 * kval.z; a0.w += q0 * kval.w;
            a1.x += q1 * kval.x; a1.y += q1 * kval.y;
            a1.z += q1 * kval.z; a1.w += q1 * kval.w;
        }
    }

    float s0[4], s1[4];
    {
        float mv[4];
        if (full) {
            float4 m4 = *(const float4*)(mask + c0);
            mv[0]=m4.x; mv[1]=m4.y; mv[2]=m4.z; mv[3]=m4.w;
        } else {
            #pragma unroll
            for (int i = 0; i < 4; i++) mv[i] = (c0 + i < C) ? mask[c0+i] : 0.f;
        }
        float av0[4] = {a0.x,a0.y,a0.z,a0.w};
        float av1[4] = {a1.x,a1.y,a1.z,a1.w};
        #pragma unroll
        for (int i = 0; i < 4; i++) {
            bool v = (c0 + i < C);
            s0[i] = v ? (av0[i] * SCALE_ + mv[i]) : -INFINITY;
            s1[i] = v ? (av1[i] * SCALE_ + mv[i]) : -INFINITY;
        }
    }

    // block max / exp / sum (head0 then head1)
    float lm0 = fmaxf(fmaxf(s0[0], s0[1]), fmaxf(s0[2], s0[3]));
    float lm1 = fmaxf(fmaxf(s1[0], s1[1]), fmaxf(s1[2], s1[3]));
    float m0 = blockMax128(lm0, red, t);
    float m1 = blockMax128(lm1, red, t);
    float p0[4], p1[4];
    float ls0 = 0.f, ls1 = 0.f;
    #pragma unroll
    for (int i = 0; i < 4; i++) {
        p0[i] = (s0[i] == -INFINITY) ? 0.f : expf(s0[i] - m0);
        p1[i] = (s1[i] == -INFINITY) ? 0.f : expf(s1[i] - m1);
        ls0 += p0[i]; ls1 += p1[i];
    }
    float l0 = blockSum128(ls0, red, t);
    float l1 = blockSum128(ls1, red, t);
    #pragma unroll
    for (int i = 0; i < 4; i++) {
        p0s[t * 4 + i] = p0[i];
        p1s[t * 4 + i] = p1[i];
    }
    __syncthreads();

    // ---- V phase: thread: dim-group dg=t&31 (dims 4dg..4dg+3), rows rg=t>>5 step 4
    int dg = t & 31;
    int rg = t >> 5;
    int rows = C - chunk * CHUNK_;
    if (rows > CHUNK_) rows = CHUNK_;
    const float4* vb = (const float4*)(vc + (size_t)kv * C * DH_
                                          + (size_t)(chunk * CHUNK_) * DH_) + dg;
    float4 va0 = {0.f,0.f,0.f,0.f}, va1 = {0.f,0.f,0.f,0.f};
    #pragma unroll 8
    for (int r = rg; r < rows; r += 4) {
        float4 vv = vb[(size_t)r * 32];
        float w0 = p0s[r], w1 = p1s[r];
        va0.x += w0 * vv.x; va0.y += w0 * vv.y; va0.z += w0 * vv.z; va0.w += w0 * vv.w;
        va1.x += w1 * vv.x; va1.y += w1 * vv.y; va1.z += w1 * vv.z; va1.w += w1 * vv.w;
    }

    int idx0 = (kv * 2) * MAXCH_ + chunk;
    int idx1 = (kv * 2 + 1) * MAXCH_ + chunk;

    vred[t] = va0; __syncthreads();
    if (t < 32) {
        float4 x0 = vred[t], x1 = vred[t+32], x2 = vred[t+64], x3 = vred[t+96];
        float4 s4;
        s4.x = x0.x+x1.x+x2.x+x3.x; s4.y = x0.y+x1.y+x2.y+x3.y;
        s4.z = x0.z+x1.z+x2.z+x3.z; s4.w = x0.w+x1.w+x2.w+x3.w;
        *(float4*)(g_acc + (size_t)idx0 * DH_ + t * 4) = s4;
    }
    __syncthreads();
    vred[t] = va1; __syncthreads();
    if (t < 32) {
        float4 x0 = vred[t], x1 = vred[t+32], x2 = vred[t+64], x3 = vred[t+96];
        float4 s4;
        s4.x = x0.x+x1.x+x2.x+x3.x; s4.y = x0.y+x1.y+x2.y+x3.y;
        s4.z = x0.z+x1.z+x2.z+x3.z; s4.w = x0.w+x1.w+x2.w+x3.w;
        *(float4*)(g_acc + (size_t)idx1 * DH_ + t * 4) = s4;
    }
    if (t == 0) { g_m[idx0] = m0; g_l[idx0] = l0; g_m[idx1] = m1; g_l[idx1] = l1; }
}

// ------------------------- 4: combine partials + new token (R2) --------------
__global__ void __launch_bounds__(512) k_attn_reduce(
                              const float* __restrict__ mask,
                              int C, int nchunks) {
    int qh = blockIdx.x, t = threadIdx.x;
    int kv = qh >> 1;
    __shared__ float sm[MAXCH_], sl[MAXCH_], sw[MAXCH_];
    __shared__ float red[8];
    __shared__ float sMax, sSnew, sL;
    __shared__ float vacc[512];

    if (t < nchunks) { sm[t] = g_m[qh * MAXCH_ + t]; sl[t] = g_l[qh * MAXCH_ + t]; }

    if (t < 128) {
        float prod = g_q[qh * DH_ + t] * g_k[kv * DH_ + t];
        float ws = warpSum(prod);
        if ((t & 31) == 0) red[t >> 5] = ws;
    }
    __syncthreads();
    if (t == 0) {
        float dot = red[0] + red[1] + red[2] + red[3];
        float s_new = dot * SCALE_ + mask[C];
        float M = s_new;
        for (int j = 0; j < nchunks; j++) M = fmaxf(M, sm[j]);
        sMax = M;
        sSnew = s_new;
    }
    __syncthreads();
    float M = sMax;
    if (t < nchunks) sw[t] = expf(sm[t] - M);
    __syncthreads();
    if (t < 64) {
        float lv = 0.f;
        for (int j = t; j < nchunks; j += 64) lv += sw[j] * sl[j];
        float ws = warpSum(lv);
        if (t == 0) red[0] = ws;
        if (t == 32) red[1] = ws;
    }
    __syncthreads();
    if (t == 0) sL = expf(sSnew - M) + red[0] + red[1];
    __syncthreads();

    int d = t & 127;
    int cg = t >> 7;
    const float* accb = g_acc + (size_t)qh * MAXCH_ * DH_ + d;
    float a = 0.f;
    #pragma unroll 8
    for (int j = cg; j < nchunks; j += 4)
        a += sw[j] * accb[(size_t)j * DH_];
    vacc[t] = a;
    __syncthreads();
    if (t < 128) {
        float wnew = expf(sSnew - M);
        float tot = vacc[t] + vacc[t + 128] + vacc[t + 256] + vacc[t + 384]
                  + wnew * g_v[kv * DH_ + t];
        g_attn[qh * DH_ + t] = tot / sL;
    }
}

// ------------------------- 5: o_proj (R2 shape) ------------------------------
__global__ void k_oproj(const float* __restrict__ Wo, float* __restrict__ out) {
    int i = blockIdx.x, t = threadIdx.x;
    const float4* W4 = (const float4*)(Wo + (size_t)i * (HQ_ * DH_));
    const float4* a4 = (const float4*)g_attn;
    float acc = 0.f;
    #pragma unroll
    for (int k = 0; k < 4; k++) {
        float4 w = W4[t + k * 128];
        float4 a = a4[t + k * 128];
        acc += w.x * a.x + w.y * a.y + w.z * a.z + w.w * a.w;
    }
    __shared__ float s[4];
    float ws = warpSum(acc);
    if ((t & 31) == 0) s[t >> 5] = ws;
    __syncthreads();
    if (t == 0) out[i] = s[0] + s[1] + s[2] + s[3];
}

// ------------------------- launch --------------------------------------------
extern "C" void kernel_launch(void* const* d_in, const int* in_sizes, int n_in,
                              void* d_out, int out_size) {
    const float* x     = (const float*)d_in[0];
    const float* cosv  = (const float*)d_in[1];
    const float* sinv  = (const float*)d_in[2];
    const float* mask  = (const float*)d_in[3];
    const float* kc    = (const float*)d_in[4];
    const float* vc    = (const float*)d_in[5];
    const float* Wq    = (const float*)d_in[6];
    const float* Wk    = (const float*)d_in[7];
    const float* Wv    = (const float*)d_in[8];
    const float* Wo    = (const float*)d_in[9];
    const float* qw    = (const float*)d_in[10];
    const float* kw    = (const float*)d_in[11];
    float* out = (float*)d_out;

    int C = in_sizes[4] / (HKV_ * DH_);           // 16384
    int nchunks = (C + CHUNK_ - 1) / CHUNK_;      // 32
    if (nchunks > MAXCH_) nchunks = MAXCH_;

    k_proj<<<4096, 128>>>(x, Wq, Wk, Wv);
    k_norm_rope<<<32, 128>>>(cosv, sinv, qw, kw, out);
    dim3 g3(nchunks, HKV_);
    k_attn_partial<<<g3, 128>>>(kc, vc, mask, C);
    k_attn_reduce<<<HQ_, 512>>>(mask, C, nchunks);
    k_oproj<<<2048, 128>>>(Wo, out);
}

// round 8
// speedup vs baseline: 1.2221x; 1.2221x over previous
#include <cuda_runtime.h>
#include <math.h>

#define H_   2048
#define HQ_  16
#define HKV_ 8
#define DH_  128
#define CHUNK_ 256
#define MAXCH_ 128
#define SCALE_ 0.08838834764831845f   // 1/sqrt(128)
#define EPS_ 1e-6f

// ------------------------- scratch (device globals, no allocs) --------------
__device__ float g_proj[4096];                 // raw q(2048) | k(1024) | v(1024)
__device__ float g_q[HQ_*DH_];                 // normed+roped q
__device__ float g_m[HQ_*MAXCH_];
__device__ float g_l[HQ_*MAXCH_];
__device__ float g_acc[HQ_*MAXCH_*DH_];
__device__ float g_attn[HQ_*DH_];              // attention out, head-major

__device__ __forceinline__ float warpSum(float v) {
    #pragma unroll
    for (int o = 16; o; o >>= 1) v += __shfl_xor_sync(0xffffffffu, v, o);
    return v;
}
__device__ __forceinline__ float warpMax(float v) {
    #pragma unroll
    for (int o = 16; o; o >>= 1) v = fmaxf(v, __shfl_xor_sync(0xffffffffu, v, o));
    return v;
}

__device__ __forceinline__ float blockSum256(float v, float* red, int t) {
    float ws = warpSum(v);
    if ((t & 31) == 0) red[t >> 5] = ws;
    __syncthreads();
    float r = (t < 8) ? red[t] : 0.f;
    r = warpSum(r);
    if (t == 0) red[8] = r;
    __syncthreads();
    float out = red[8];
    __syncthreads();
    return out;
}
__device__ __forceinline__ float blockMax256(float v, float* red, int t) {
    float ws = warpMax(v);
    if ((t & 31) == 0) red[t >> 5] = ws;
    __syncthreads();
    float r = (t < 8) ? red[t] : -INFINITY;
    r = warpMax(r);
    if (t == 0) red[8] = r;
    __syncthreads();
    float out = red[8];
    __syncthreads();
    return out;
}

// ------------------------- 1: Q projection only ------------------------------
// 2048 blocks x 128 threads (R2 shape, Wq only).
__global__ void k_qproj(const float* __restrict__ x,
                        const float* __restrict__ Wq) {
    int e = blockIdx.x;
    int t = threadIdx.x;
    const float4* W4 = (const float4*)(Wq + (size_t)e * H_);
    const float4* x4 = (const float4*)x;
    float acc = 0.f;
    #pragma unroll
    for (int k = 0; k < 4; k++) {
        float4 w  = W4[t + k * 128];
        float4 xv = x4[t + k * 128];
        acc += w.x * xv.x + w.y * xv.y + w.z * xv.z + w.w * xv.w;
    }
    __shared__ float s[4];
    float ws = warpSum(acc);
    if ((t & 31) == 0) s[t >> 5] = ws;
    __syncthreads();
    if (t == 0) g_proj[e] = s[0] + s[1] + s[2] + s[3];
}

// ------------------------- 2: Q RMSNorm + RoPE -------------------------------
// 16 blocks x 128 threads.
__global__ void k_qnorm(const float* __restrict__ cosv,
                        const float* __restrict__ sinv,
                        const float* __restrict__ qw) {
    int b = blockIdx.x, t = threadIdx.x;
    __shared__ float sx[DH_];
    __shared__ float red[8];
    float x = g_proj[b * DH_ + t];
    float ws = warpSum(x * x);
    if ((t & 31) == 0) red[t >> 5] = ws;
    __syncthreads();
    float ssum = red[0] + red[1] + red[2] + red[3];
    float rms = sqrtf(ssum * (1.0f / DH_) + EPS_);
    float xn = x / rms * qw[t];
    sx[t] = xn;
    __syncthreads();
    float rot = (t < 64) ? -sx[t + 64] : sx[t - 64];
    g_q[b * DH_ + t] = xn * cosv[t] + rot * sinv[t];
}

// ------------------------- 3: partial + overlapped KV projection -------------
// grid (nchunks*8 + 1024) x 256 threads.
// bx < partialBlocks : R2 attention partial (chunk = bx % nchunks, kv = bx / nchunks)
// else               : KV projection, 2 rows per block (half-block dot each)
__global__ void __launch_bounds__(256) k_partial_mix(
                               const float* __restrict__ kc,
                               const float* __restrict__ vc,
                               const float* __restrict__ mask,
                               const float* __restrict__ x,
                               const float* __restrict__ Wk,
                               const float* __restrict__ Wv,
                               int C, int nchunks) {
    int bx = blockIdx.x;
    int t = threadIdx.x;
    int partialBlocks = nchunks * HKV_;

    if (bx >= partialBlocks) {
        // ---------------- KV projection: 2 rows of combined [k(1024)|v(1024)] --
        int pb = bx - partialBlocks;           // 0..1023
        int h  = t >> 7;                       // half-block 0/1
        int tt = t & 127;
        int r  = pb * 2 + h;                   // combined row 0..2047
        const float* W = (r < 1024) ? (Wk + (size_t)r * H_)
                                    : (Wv + (size_t)(r - 1024) * H_);
        const float4* W4 = (const float4*)W;
        const float4* x4 = (const float4*)x;
        float acc = 0.f;
        #pragma unroll
        for (int k = 0; k < 4; k++) {
            float4 w  = W4[tt + k * 128];
            float4 xv = x4[tt + k * 128];
            acc += w.x * xv.x + w.y * xv.y + w.z * xv.z + w.w * xv.w;
        }
        __shared__ float s[8];
        float ws = warpSum(acc);
        if ((t & 31) == 0) s[t >> 5] = ws;
        __syncthreads();
        if (tt == 0) {
            int b0 = h * 4;
            g_proj[2048 + r] = s[b0] + s[b0+1] + s[b0+2] + s[b0+3];
        }
        return;
    }

    // ---------------- attention partial (R2 verbatim) -------------------------
    int chunk = bx % nchunks;
    int kv = bx / nchunks;
    int c = chunk * CHUNK_ + t;
    bool valid = (c < C);

    __shared__ float q0s[DH_], q1s[DH_];
    __shared__ float p0s[CHUNK_], p1s[CHUNK_];
    __shared__ float red[16];
    __shared__ float vred[CHUNK_];

    if (t < DH_) {
        q0s[t] = g_q[(kv * 2) * DH_ + t];
        q1s[t] = g_q[(kv * 2 + 1) * DH_ + t];
    }
    __syncthreads();

    float a0 = 0.f, a1 = 0.f;
    if (valid) {
        const float* kbase = kc + (size_t)kv * DH_ * C + c;
        #pragma unroll 16
        for (int d = 0; d < DH_; d++) {
            float kval = kbase[(size_t)d * C];
            a0 += q0s[d] * kval;
            a1 += q1s[d] * kval;
        }
    }
    float mval = valid ? mask[c] : 0.f;
    float s0 = valid ? (a0 * SCALE_ + mval) : -INFINITY;
    float s1 = valid ? (a1 * SCALE_ + mval) : -INFINITY;

    float m0 = blockMax256(s0, red, t);
    float m1 = blockMax256(s1, red, t);
    float p0 = valid ? expf(s0 - m0) : 0.f;
    float p1 = valid ? expf(s1 - m1) : 0.f;
    float l0 = blockSum256(p0, red, t);
    float l1 = blockSum256(p1, red, t);
    p0s[t] = p0; p1s[t] = p1;
    __syncthreads();

    int d = t & 127;
    int half = t >> 7;
    const float* vbase = vc + (size_t)kv * C * DH_ + (size_t)(chunk * CHUNK_) * DH_ + d;
    float va0 = 0.f, va1 = 0.f;
    int cmax = C - chunk * CHUNK_;
    if (cmax > CHUNK_) cmax = CHUNK_;
    #pragma unroll 8
    for (int cc = half; cc < cmax; cc += 2) {
        float vv = vbase[(size_t)cc * DH_];
        va0 += p0s[cc] * vv;
        va1 += p1s[cc] * vv;
    }
    vred[t] = va0; __syncthreads();
    float tot0 = (t < 128) ? (vred[t] + vred[t + 128]) : 0.f;
    __syncthreads();
    vred[t] = va1; __syncthreads();
    float tot1 = (t < 128) ? (vred[t] + vred[t + 128]) : 0.f;

    int idx0 = (kv * 2) * MAXCH_ + chunk;
    int idx1 = (kv * 2 + 1) * MAXCH_ + chunk;
    if (t == 0) { g_m[idx0] = m0; g_l[idx0] = l0; g_m[idx1] = m1; g_l[idx1] = l1; }
    if (t < 128) {
        g_acc[(size_t)idx0 * DH_ + t] = tot0;
        g_acc[(size_t)idx1 * DH_ + t] = tot1;
    }
}

// ------------------------- 4: reduce + fused KV norm/rope + outputs ----------
// grid 16 blocks (one per q head) x 512 threads. (R2 reduce + k-norm prologue)
__global__ void __launch_bounds__(512) k_reduce_kv(
                              const float* __restrict__ mask,
                              const float* __restrict__ cosv,
                              const float* __restrict__ sinv,
                              const float* __restrict__ kw,
                              float* __restrict__ out,
                              int C, int nchunks) {
    int qh = blockIdx.x, t = threadIdx.x;
    int kv = qh >> 1;
    __shared__ float sk[DH_];
    __shared__ float sm[MAXCH_], sl[MAXCH_], sw[MAXCH_];
    __shared__ float red[8];
    __shared__ float sMax, sSnew, sL;
    __shared__ float vacc[512];

    // ---- k norm + rope for this kv head (threads 0..127) ----
    float xk = 0.f;
    if (t < 128) {
        xk = g_proj[2048 + kv * DH_ + t];
        float ws = warpSum(xk * xk);
        if ((t & 31) == 0) red[t >> 5] = ws;
    }
    __syncthreads();
    if (t < 128) {
        float ssum = red[0] + red[1] + red[2] + red[3];
        float rms = sqrtf(ssum * (1.0f / DH_) + EPS_);
        sk[t] = xk / rms * kw[t];
    }
    __syncthreads();
    float ko = 0.f;
    if (t < 128) {
        float rot = (t < 64) ? -sk[t + 64] : sk[t - 64];
        ko = sk[t] * cosv[t] + rot * sinv[t];
    }
    __syncthreads();
    if (t < 128) sk[t] = ko;
    // designated writer: even qh writes k_new + v outputs
    if ((qh & 1) == 0 && t < 128) {
        out[2048 + kv * DH_ + t] = ko;
        out[3072 + kv * DH_ + t] = g_proj[3072 + kv * DH_ + t];
    }
    __syncthreads();

    // ---- partial m/l + new-token score ----
    if (t < nchunks) { sm[t] = g_m[qh * MAXCH_ + t]; sl[t] = g_l[qh * MAXCH_ + t]; }
    if (t < 128) {
        float prod = g_q[qh * DH_ + t] * sk[t];
        float ws = warpSum(prod);
        if ((t & 31) == 0) red[t >> 5] = ws;
    }
    __syncthreads();
    if (t == 0) {
        float dot = red[0] + red[1] + red[2] + red[3];
        float s_new = dot * SCALE_ + mask[C];
        float M = s_new;
        for (int j = 0; j < nchunks; j++) M = fmaxf(M, sm[j]);
        sMax = M;
        sSnew = s_new;
    }
    __syncthreads();
    float M = sMax;
    if (t < nchunks) sw[t] = expf(sm[t] - M);
    __syncthreads();
    if (t < 64) {
        float lv = 0.f;
        for (int j = t; j < nchunks; j += 64) lv += sw[j] * sl[j];
        float ws = warpSum(lv);
        if (t == 0) red[0] = ws;
        if (t == 32) red[1] = ws;
    }
    __syncthreads();
    if (t == 0) sL = expf(sSnew - M) + red[0] + red[1];
    __syncthreads();

    int d = t & 127;
    int cg = t >> 7;
    const float* accb = g_acc + (size_t)qh * MAXCH_ * DH_ + d;
    float a = 0.f;
    #pragma unroll 8
    for (int j = cg; j < nchunks; j += 4)
        a += sw[j] * accb[(size_t)j * DH_];
    vacc[t] = a;
    __syncthreads();
    if (t < 128) {
        float wnew = expf(sSnew - M);
        float tot = vacc[t] + vacc[t + 128] + vacc[t + 256] + vacc[t + 384]
                  + wnew * g_proj[3072 + kv * DH_ + t];   // v_new (raw proj)
        g_attn[qh * DH_ + t] = tot / sL;
    }
}

// ------------------------- 5: o_proj (R2 shape) ------------------------------
__global__ void k_oproj(const float* __restrict__ Wo, float* __restrict__ out) {
    int i = blockIdx.x, t = threadIdx.x;
    const float4* W4 = (const float4*)(Wo + (size_t)i * (HQ_ * DH_));
    const float4* a4 = (const float4*)g_attn;
    float acc = 0.f;
    #pragma unroll
    for (int k = 0; k < 4; k++) {
        float4 w = W4[t + k * 128];
        float4 a = a4[t + k * 128];
        acc += w.x * a.x + w.y * a.y + w.z * a.z + w.w * a.w;
    }
    __shared__ float s[4];
    float ws = warpSum(acc);
    if ((t & 31) == 0) s[t >> 5] = ws;
    __syncthreads();
    if (t == 0) out[i] = s[0] + s[1] + s[2] + s[3];
}

// ------------------------- launch --------------------------------------------
extern "C" void kernel_launch(void* const* d_in, const int* in_sizes, int n_in,
                              void* d_out, int out_size) {
    const float* x     = (const float*)d_in[0];
    const float* cosv  = (const float*)d_in[1];
    const float* sinv  = (const float*)d_in[2];
    const float* mask  = (const float*)d_in[3];
    const float* kc    = (const float*)d_in[4];
    const float* vc    = (const float*)d_in[5];
    const float* Wq    = (const float*)d_in[6];
    const float* Wk    = (const float*)d_in[7];
    const float* Wv    = (const float*)d_in[8];
    const float* Wo    = (const float*)d_in[9];
    const float* qw    = (const float*)d_in[10];
    const float* kw    = (const float*)d_in[11];
    float* out = (float*)d_out;

    int C = in_sizes[4] / (HKV_ * DH_);           // 16384
    int nchunks = (C + CHUNK_ - 1) / CHUNK_;      // 64
    if (nchunks > MAXCH_) nchunks = MAXCH_;

    k_qproj<<<2048, 128>>>(x, Wq);
    k_qnorm<<<HQ_, 128>>>(cosv, sinv, qw);
    int mixBlocks = nchunks * HKV_ + 1024;        // 512 partial + 1024 kvproj
    k_partial_mix<<<mixBlocks, 256>>>(kc, vc, mask, x, Wk, Wv, C, nchunks);
    k_reduce_kv<<<HQ_, 512>>>(mask, cosv, sinv, kw, out, C, nchunks);
    k_oproj<<<2048, 128>>>(Wo, out);
}

// round 9
// speedup vs baseline: 1.2708x; 1.0399x over previous
#include <cuda_runtime.h>
#include <math.h>

#define H_   2048
#define HQ_  16
#define HKV_ 8
#define DH_  128
#define CHUNK_ 256
#define MAXCH_ 128
#define GRID_ 512
#define SCALE_ 0.08838834764831845f   // 1/sqrt(128)
#define EPS_ 1e-6f

// ------------------------- scratch (device globals, no allocs) --------------
__device__ float g_proj[4096];                 // raw q(2048) | k(1024) | v(1024)
__device__ float g_q[HQ_*DH_];                 // normed+roped q
__device__ float g_k[HKV_*DH_];                // normed+roped k_new
__device__ float g_v[HKV_*DH_];                // v_new
__device__ float g_m[HQ_*MAXCH_];
__device__ float g_l[HQ_*MAXCH_];
__device__ float g_acc[HQ_*MAXCH_*DH_];
__device__ float g_attn[HQ_*DH_];              // attention out, head-major

// grid barrier state (epoch-based; survives graph replays)
__device__ unsigned g_bar_count = 0;
__device__ volatile unsigned g_bar_epoch = 0;

__device__ __forceinline__ void gridBarrier() {
    __syncthreads();
    if (threadIdx.x == 0) {
        unsigned e = g_bar_epoch;
        __threadfence();
        unsigned r = atomicAdd(&g_bar_count, 1u);
        if (r == gridDim.x - 1) {
            g_bar_count = 0;
            __threadfence();
            g_bar_epoch = e + 1;
        } else {
            while (g_bar_epoch == e) __nanosleep(64);
        }
        __threadfence();
    }
    __syncthreads();
}

__device__ __forceinline__ float warpSum(float v) {
    #pragma unroll
    for (int o = 16; o; o >>= 1) v += __shfl_xor_sync(0xffffffffu, v, o);
    return v;
}
__device__ __forceinline__ float warpMax(float v) {
    #pragma unroll
    for (int o = 16; o; o >>= 1) v = fmaxf(v, __shfl_xor_sync(0xffffffffu, v, o));
    return v;
}

__device__ __forceinline__ float blockSum256(float v, float* red, int t) {
    float ws = warpSum(v);
    if ((t & 31) == 0) red[t >> 5] = ws;
    __syncthreads();
    float r = (t < 8) ? red[t] : 0.f;
    r = warpSum(r);
    if (t == 0) red[8] = r;
    __syncthreads();
    float out = red[8];
    __syncthreads();
    return out;
}
__device__ __forceinline__ float blockMax256(float v, float* red, int t) {
    float ws = warpMax(v);
    if ((t & 31) == 0) red[t >> 5] = ws;
    __syncthreads();
    float r = (t < 8) ? red[t] : -INFINITY;
    r = warpMax(r);
    if (t == 0) red[8] = r;
    __syncthreads();
    float out = red[8];
    __syncthreads();
    return out;
}

// ------------------------- the persistent kernel ----------------------------
__global__ void __launch_bounds__(256, 4) k_fused(
        const float* __restrict__ x,
        const float* __restrict__ cosv,
        const float* __restrict__ sinv,
        const float* __restrict__ mask,
        const float* __restrict__ kc,
        const float* __restrict__ vc,
        const float* __restrict__ Wq,
        const float* __restrict__ Wk,
        const float* __restrict__ Wv,
        const float* __restrict__ Wo,
        const float* __restrict__ qw,
        const float* __restrict__ kw,
        float* __restrict__ out,
        int C, int nchunks) {
    int bx = blockIdx.x;
    int t = threadIdx.x;
    int warp = t >> 5, lane = t & 31;

    // ============ P0: QKV projection (warp-per-output, 8/block) =============
    {
        int e = bx * 8 + warp;                 // 0..4095
        const float* W = (e < 2048) ? (Wq + (size_t)e * H_)
                       : (e < 3072) ? (Wk + (size_t)(e - 2048) * H_)
                                    : (Wv + (size_t)(e - 3072) * H_);
        const float4* W4 = (const float4*)W;
        const float4* x4 = (const float4*)x;
        float acc = 0.f;
        #pragma unroll
        for (int i = 0; i < 16; i++) {
            float4 w  = W4[lane + i * 32];
            float4 xv = x4[lane + i * 32];
            acc += w.x * xv.x + w.y * xv.y + w.z * xv.z + w.w * xv.w;
        }
        acc = warpSum(acc);
        if (lane == 0) g_proj[e] = acc;
    }
    gridBarrier();

    // ============ P1: RMSNorm + RoPE + output copies (blocks 0..31) ==========
    if (bx < 32 && t < 128) {
        __shared__ float sx[DH_];
        __shared__ float red1[4];
        int b = bx;
        const float* row = g_proj + b * DH_;
        if (b < 24) {
            bool isq = (b < 16);
            float xv = row[t];
            float ws = warpSum(xv * xv);
            if ((t & 31) == 0) red1[t >> 5] = ws;
            __syncwarp();
            // need all 4 warps of first 128 threads; use bar for first 128 via syncthreads-free trick:
            // simpler: all 256 threads hit syncthreads below (threads >=128 skip compute)
            sx[t] = xv;               // stage raw
            // fallthrough to cooperative section below
            (void)isq;
        } else {
            int kv = b - 24;
            float v = row[t];
            g_v[kv * DH_ + t] = v;
            out[3072 + kv * DH_ + t] = v;
        }
    }
    // cooperative RMSNorm for blocks 0..23 (all 256 threads participate in syncs)
    if (bx < 24) {
        __shared__ float sx2[DH_];
        __shared__ float red2[16];
        int b = bx;
        bool isq = (b < 16);
        float xv = (t < 128) ? g_proj[b * DH_ + t] : 0.f;
        float ws = warpSum(xv * xv);
        if ((t & 31) == 0) red2[t >> 5] = ws;
        __syncthreads();
        float ssum = red2[0] + red2[1] + red2[2] + red2[3];
        float rms = sqrtf(ssum * (1.0f / DH_) + EPS_);
        float xn = (t < 128) ? xv / rms * (isq ? qw[t] : kw[t]) : 0.f;
        if (t < 128) sx2[t] = xn;
        __syncthreads();
        if (t < 128) {
            float rot = (t < 64) ? -sx2[t + 64] : sx2[t - 64];
            float o = xn * cosv[t] + rot * sinv[t];
            if (isq) {
                g_q[b * DH_ + t] = o;
            } else {
                int kv = b - 16;
                g_k[kv * DH_ + t] = o;
                out[2048 + kv * DH_ + t] = o;
            }
        }
    }
    gridBarrier();

    // ============ P2: attention partial (R2 verbatim; task = bx) =============
    {
        int chunk = bx % nchunks;
        int kv = bx / nchunks;
        int c = chunk * CHUNK_ + t;
        bool valid = (c < C) && (kv < HKV_);

        __shared__ float q0s[DH_], q1s[DH_];
        __shared__ float p0s[CHUNK_], p1s[CHUNK_];
        __shared__ float red[16];
        __shared__ float vred[CHUNK_];

        if (kv < HKV_) {
            if (t < DH_) {
                q0s[t] = g_q[(kv * 2) * DH_ + t];
                q1s[t] = g_q[(kv * 2 + 1) * DH_ + t];
            }
            __syncthreads();

            float a0 = 0.f, a1 = 0.f;
            if (valid) {
                const float* kbase = kc + (size_t)kv * DH_ * C + c;
                #pragma unroll 16
                for (int d = 0; d < DH_; d++) {
                    float kval = kbase[(size_t)d * C];
                    a0 += q0s[d] * kval;
                    a1 += q1s[d] * kval;
                }
            }
            float mval = valid ? mask[c] : 0.f;
            float s0 = valid ? (a0 * SCALE_ + mval) : -INFINITY;
            float s1 = valid ? (a1 * SCALE_ + mval) : -INFINITY;

            float m0 = blockMax256(s0, red, t);
            float m1 = blockMax256(s1, red, t);
            float p0 = valid ? expf(s0 - m0) : 0.f;
            float p1 = valid ? expf(s1 - m1) : 0.f;
            float l0 = blockSum256(p0, red, t);
            float l1 = blockSum256(p1, red, t);
            p0s[t] = p0; p1s[t] = p1;
            __syncthreads();

            int d = t & 127;
            int half = t >> 7;
            const float* vbase = vc + (size_t)kv * C * DH_ + (size_t)(chunk * CHUNK_) * DH_ + d;
            float va0 = 0.f, va1 = 0.f;
            int cmax = C - chunk * CHUNK_;
            if (cmax > CHUNK_) cmax = CHUNK_;
            #pragma unroll 8
            for (int cc = half; cc < cmax; cc += 2) {
                float vv = vbase[(size_t)cc * DH_];
                va0 += p0s[cc] * vv;
                va1 += p1s[cc] * vv;
            }
            vred[t] = va0; __syncthreads();
            float tot0 = (t < 128) ? (vred[t] + vred[t + 128]) : 0.f;
            __syncthreads();
            vred[t] = va1; __syncthreads();
            float tot1 = (t < 128) ? (vred[t] + vred[t + 128]) : 0.f;

            int idx0 = (kv * 2) * MAXCH_ + chunk;
            int idx1 = (kv * 2 + 1) * MAXCH_ + chunk;
            if (t == 0) { g_m[idx0] = m0; g_l[idx0] = l0; g_m[idx1] = m1; g_l[idx1] = l1; }
            if (t < 128) {
                g_acc[(size_t)idx0 * DH_ + t] = tot0;
                g_acc[(size_t)idx1 * DH_ + t] = tot1;
            }
        }
    }
    gridBarrier();

    // ============ P3: combine partials (blocks 0..15) ========================
    if (bx < HQ_) {
        int qh = bx;
        int kv = qh >> 1;
        __shared__ float sm[MAXCH_], sl[MAXCH_], sw[MAXCH_];
        __shared__ float red3[8];
        __shared__ float sMax, sSnew, sL;
        __shared__ float vacc[256];

        if (t < nchunks) { sm[t] = g_m[qh * MAXCH_ + t]; sl[t] = g_l[qh * MAXCH_ + t]; }
        if (t < 128) {
            float prod = g_q[qh * DH_ + t] * g_k[kv * DH_ + t];
            float ws = warpSum(prod);
            if ((t & 31) == 0) red3[t >> 5] = ws;
        }
        __syncthreads();
        if (t == 0) {
            float dot = red3[0] + red3[1] + red3[2] + red3[3];
            float s_new = dot * SCALE_ + mask[C];
            float M = s_new;
            for (int j = 0; j < nchunks; j++) M = fmaxf(M, sm[j]);
            sMax = M;
            sSnew = s_new;
        }
        __syncthreads();
        float M = sMax;
        if (t < nchunks) sw[t] = expf(sm[t] - M);
        __syncthreads();
        if (t < 64) {
            float lv = 0.f;
            for (int j = t; j < nchunks; j += 64) lv += sw[j] * sl[j];
            float ws = warpSum(lv);
            if (t == 0) red3[0] = ws;
            if (t == 32) red3[1] = ws;
        }
        __syncthreads();
        if (t == 0) sL = expf(sSnew - M) + red3[0] + red3[1];
        __syncthreads();

        int d = t & 127;
        int cg = t >> 7;                       // 0..1
        const float* accb = g_acc + (size_t)qh * MAXCH_ * DH_ + d;
        float a = 0.f;
        #pragma unroll 8
        for (int j = cg; j < nchunks; j += 2)
            a += sw[j] * accb[(size_t)j * DH_];
        vacc[t] = a;
        __syncthreads();
        if (t < 128) {
            float wnew = expf(sSnew - M);
            float tot = vacc[t] + vacc[t + 128] + wnew * g_v[kv * DH_ + t];
            g_attn[qh * DH_ + t] = tot / sL;
        }
    }
    gridBarrier();

    // ============ P4: o_proj (warp-per-output, blocks 0..255) ================
    if (bx < 256) {
        int i = bx * 8 + warp;                 // 0..2047
        const float4* W4 = (const float4*)(Wo + (size_t)i * (HQ_ * DH_));
        const float4* a4 = (const float4*)g_attn;
        float acc = 0.f;
        #pragma unroll
        for (int k = 0; k < 16; k++) {
            float4 w = W4[lane + k * 32];
            float4 a = a4[lane + k * 32];
            acc += w.x * a.x + w.y * a.y + w.z * a.z + w.w * a.w;
        }
        acc = warpSum(acc);
        if (lane == 0) out[i] = acc;
    }
}

// ------------------------- launch --------------------------------------------
extern "C" void kernel_launch(void* const* d_in, const int* in_sizes, int n_in,
                              void* d_out, int out_size) {
    const float* x     = (const float*)d_in[0];
    const float* cosv  = (const float*)d_in[1];
    const float* sinv  = (const float*)d_in[2];
    const float* mask  = (const float*)d_in[3];
    const float* kc    = (const float*)d_in[4];
    const float* vc    = (const float*)d_in[5];
    const float* Wq    = (const float*)d_in[6];
    const float* Wk    = (const float*)d_in[7];
    const float* Wv    = (const float*)d_in[8];
    const float* Wo    = (const float*)d_in[9];
    const float* qw    = (const float*)d_in[10];
    const float* kw    = (const float*)d_in[11];
    float* out = (float*)d_out;

    int C = in_sizes[4] / (HKV_ * DH_);           // 16384
    int nchunks = (C + CHUNK_ - 1) / CHUNK_;      // 64
    if (nchunks > MAXCH_) nchunks = MAXCH_;

    k_fused<<<GRID_, 256>>>(x, cosv, sinv, mask, kc, vc,
                            Wq, Wk, Wv, Wo, qw, kw, out, C, nchunks);
}